// round 4
// baseline (speedup 1.0000x reference)
#include <cuda_runtime.h>
#include <math.h>

// Problem constants (fixed shapes)
#define BB   8
#define CC   512
#define LL   8192
#define NN   512        // LL / 16 chunks
#define CO   64         // CC / 8
#define CS   16
#define NT   16         // chunks per SE block (256 timesteps)

// Scratch (allocation-free rule: __device__ global)
__device__ float g_e[BB * CC * NN];      // EMA output  [B][C][N]  (8 MB)

// ---------------------------------------------------------------------------
// Kernel 1: chunk mean + causal EMA scan.
// One block per (b,c) row. 512 threads, one chunk each.
// y_t = g*y_{t-1} + (1-g)*mean_t  as an affine parallel scan.
// ---------------------------------------------------------------------------
__global__ __launch_bounds__(512) void k_mean_ema(const float* __restrict__ x,
                                                  const float* __restrict__ gamma) {
    const int row = blockIdx.x;            // b*CC + c
    const int c   = row & (CC - 1);
    const int t   = threadIdx.x;

    const float4* xr = reinterpret_cast<const float4*>(x) + (size_t)row * (LL / 4);

    __shared__ __align__(16) float f4sum[LL / 4];   // 2048 floats = 8 KB
    __shared__ float wa[16], wb[16];

#pragma unroll
    for (int k = 0; k < 4; k++) {
        float4 v = __ldcs(&xr[t + 512 * k]);        // streaming: no L2 reuse
        f4sum[t + 512 * k] = v.x + v.y + v.z + v.w;
    }
    __syncthreads();

    float4 cs = reinterpret_cast<const float4*>(f4sum)[t];
    float mean = (cs.x + cs.y + cs.z + cs.w) * (1.0f / 16.0f);

    const float g = gamma[c];
    float a  = g;                      // affine: y -> a*y + b
    float bb = (1.0f - g) * mean;

    const int lane = t & 31, warp = t >> 5;
#pragma unroll
    for (int off = 1; off < 32; off <<= 1) {
        float pa = __shfl_up_sync(0xffffffffu, a,  off);
        float pb = __shfl_up_sync(0xffffffffu, bb, off);
        if (lane >= off) { bb = a * pb + bb; a = a * pa; }
    }
    if (lane == 31) { wa[warp] = a; wb[warp] = bb; }
    __syncthreads();

    float prevB = 0.0f;
    for (int w = 0; w < warp; w++) prevB = wa[w] * prevB + wb[w];

    g_e[(size_t)row * NN + t] = a * prevB + bb;
}

// ---------------------------------------------------------------------------
// Kernel 2 (fully fused SE + apply):
//   gate = sigmoid(w2 @ relu(w1 @ e + b1) + b2);  out = repeat(gate,16) * x
// One block per (batch, 16-chunk n-tile): grid (32, 8) = 256 blocks, 256 thr.
// Phase A: h[64 x 16] = relu(w1[64x512] @ e[512x16] + b1)           -> smem
// Phase B: per 64-channel tile: gate[64 x 16] -> smem, then stream
//          the matching 64 KB of x: out = gate * x.
// ---------------------------------------------------------------------------
__global__ __launch_bounds__(256) void k_se_apply(const float* __restrict__ x,
                                                  const float* __restrict__ w1,
                                                  const float* __restrict__ b1,
                                                  const float* __restrict__ w2,
                                                  const float* __restrict__ b2,
                                                  float* __restrict__ out) {
    const int b  = blockIdx.y;
    const int N0 = blockIdx.x * NT;                 // first chunk of this tile
    const float* e = g_e + (size_t)b * CC * NN;

    __shared__ __align__(16) float se [64 * 20];    // e tile  [cc][n], pad 20
    __shared__ float             swt[64 * 65];      // weights transposed [k][out]
    __shared__ __align__(16) float sh [64 * 20];    // h tile  [o][n],  pad 20
    __shared__ __align__(16) float sgt[64 * 20];    // gate tile [c][n], pad 20

    const int t  = threadIdx.x;
    const int nx = t & 3;        // n quad: n = nx*4 + j  (j=0..3)
    const int ox = t >> 2;       // output index 0..63

    // ---------- Phase A: GEMM1 (K = 512 in 8 tiles of 64) ----------
    float acc[4] = {};

    for (int c0 = 0; c0 < CC; c0 += 64) {
        // stage e[64cc x 16n]  (1024 elems, 4/thread)
#pragma unroll
        for (int i = 0; i < 4; i++) {
            int idx = t + i * 256;
            int cc = idx >> 4, nn = idx & 15;
            se[cc * 20 + nn] = e[(size_t)(c0 + cc) * NN + N0 + nn];
        }
        // stage w1[o][c0+cc] -> swt[cc][o]  (4096 elems, 16/thread, coalesced on cc)
#pragma unroll
        for (int i = 0; i < 16; i++) {
            int idx = t + i * 256;
            int o = idx >> 6, cc = idx & 63;
            swt[cc * 65 + o] = w1[(size_t)o * CC + c0 + cc];
        }
        __syncthreads();

#pragma unroll
        for (int cc = 0; cc < 64; cc++) {
            float4 bv = *reinterpret_cast<const float4*>(&se[cc * 20 + nx * 4]);
            float a = swt[cc * 65 + ox];
            acc[0] += a * bv.x; acc[1] += a * bv.y; acc[2] += a * bv.z; acc[3] += a * bv.w;
        }
        __syncthreads();
    }

    {   // h = relu(acc + b1)  -> sh
        float bias = b1[ox];
        float4 v;
        v.x = fmaxf(acc[0] + bias, 0.0f);
        v.y = fmaxf(acc[1] + bias, 0.0f);
        v.z = fmaxf(acc[2] + bias, 0.0f);
        v.w = fmaxf(acc[3] + bias, 0.0f);
        *reinterpret_cast<float4*>(&sh[ox * 20 + nx * 4]) = v;
    }
    __syncthreads();

    // ---------- Phase B: GEMM2 + sigmoid + streaming apply, 8 c-tiles ----------
    // x/out float4 base for this block's timestep window (256 timesteps)
    const size_t xbase = ((size_t)b * CC) * (LL / 4) + (size_t)blockIdx.x * 64;

    for (int cb = 0; cb < 8; cb++) {
        const int c0 = cb * 64;
        // stage w2[(c0+c)][k] -> swt[k][c]  (coalesced on k)
#pragma unroll
        for (int i = 0; i < 16; i++) {
            int idx = t + i * 256;
            int c = idx >> 6, k = idx & 63;
            swt[k * 65 + c] = w2[(size_t)(c0 + c) * CO + k];
        }
        __syncthreads();

        float a2[4] = {};
#pragma unroll
        for (int k = 0; k < 64; k++) {
            float4 bv = *reinterpret_cast<const float4*>(&sh[k * 20 + nx * 4]);
            float a = swt[k * 65 + ox];
            a2[0] += a * bv.x; a2[1] += a * bv.y; a2[2] += a * bv.z; a2[3] += a * bv.w;
        }
        {
            float bias = b2[c0 + ox];
            float4 v;
            v.x = 1.0f / (1.0f + __expf(-(a2[0] + bias)));
            v.y = 1.0f / (1.0f + __expf(-(a2[1] + bias)));
            v.z = 1.0f / (1.0f + __expf(-(a2[2] + bias)));
            v.w = 1.0f / (1.0f + __expf(-(a2[3] + bias)));
            *reinterpret_cast<float4*>(&sgt[ox * 20 + nx * 4]) = v;
        }
        __syncthreads();

        // stream x for channels [c0, c0+64), 256 timesteps: 4096 float4
        // idx -> (cl = idx>>6, col = idx&63); lanes of a warp share cl (coalesced 512B)
#pragma unroll 4
        for (int i = 0; i < 16; i++) {
            int idx = t + i * 256;
            int cl = idx >> 6, col = idx & 63;
            size_t off = xbase + (size_t)(c0 + cl) * (LL / 4) + col;
            float4 v = __ldcs(&reinterpret_cast<const float4*>(x)[off]);  // stream
            float g = sgt[cl * 20 + (col >> 2)];
            float4 o;
            o.x = v.x * g; o.y = v.y * g; o.z = v.z * g; o.w = v.w * g;
            __stcs(&reinterpret_cast<float4*>(out)[off], o);              // evict-first
        }
        __syncthreads();   // sgt/swt reuse next c-tile
    }
}

// ---------------------------------------------------------------------------
extern "C" void kernel_launch(void* const* d_in, const int* in_sizes, int n_in,
                              void* d_out, int out_size) {
    const float* x     = (const float*)d_in[0];
    const float* gamma = (const float*)d_in[1];
    const float* w1    = (const float*)d_in[2];
    const float* b1    = (const float*)d_in[3];
    const float* w2    = (const float*)d_in[4];
    const float* b2    = (const float*)d_in[5];
    float* out = (float*)d_out;

    k_mean_ema<<<BB * CC, 512>>>(x, gamma);
    k_se_apply<<<dim3(NN / NT, BB), 256>>>(x, w1, b1, w2, b2, out);
}